// round 15
// baseline (speedup 1.0000x reference)
#include <cuda_runtime.h>
#include <cuda_fp16.h>
#include <cstdint>

#define NN 100000
#define EE 1600000
#define DD 128
#define GG 64
#define CC 2
#define EPSBN 1e-5f

// ---------------- scratch (static device globals; no allocation) ----------------
__device__ __half g_bufA[(size_t)NN * DD];
__device__ __half g_bufB[(size_t)NN * DD];
__device__ float g_dinv[NN];
__device__ unsigned long long g_packed[NN];   // hi32: count, lo32: fixed-point weight sum
__device__ int   g_offs[NN + 1];
__device__ int   g_cursor[NN];
__device__ int   g_bsums[512];
__device__ int2  g_cpack[EE];
__device__ float g_stats[512];          // [0:256) layer0 raw sums, [256:512) layer1
__device__ float g_pool[GG * 8 * DD];
__device__ float g_pcnt[GG];
__device__ __half g_wt[4 * 128 * 128];  // fp16 weights, TRANSPOSED: [n][k]

// ---------------- helpers ----------------
__device__ __forceinline__ uint32_t smem_u32(const void* p) {
    uint32_t a;
    asm("{ .reg .u64 t; cvta.to.shared.u64 t, %1; cvt.u32.u64 %0, t; }" : "=r"(a) : "l"(p));
    return a;
}
__device__ __forceinline__ void mma_f16(float* d, const uint32_t* a, const uint32_t* b) {
    asm volatile(
        "mma.sync.aligned.m16n8k16.row.col.f32.f16.f16.f32 "
        "{%0,%1,%2,%3}, {%4,%5,%6,%7}, {%8,%9}, {%0,%1,%2,%3};"
        : "+f"(d[0]), "+f"(d[1]), "+f"(d[2]), "+f"(d[3])
        : "r"(a[0]), "r"(a[1]), "r"(a[2]), "r"(a[3]), "r"(b[0]), "r"(b[1]));
}
__device__ __forceinline__ void ldsm4(uint32_t* a, uint32_t addr) {
    asm volatile("ldmatrix.sync.aligned.m8n8.x4.shared.b16 {%0,%1,%2,%3}, [%4];"
        : "=r"(a[0]), "=r"(a[1]), "=r"(a[2]), "=r"(a[3]) : "r"(addr));
}
__device__ __forceinline__ void cp_async16(uint32_t saddr, const void* gaddr) {
    asm volatile("cp.async.cg.shared.global [%0], [%1], 16;" :: "r"(saddr), "l"(gaddr));
}
__device__ __forceinline__ unsigned long long pack_w(float w) {
    return (1ull << 32) | (unsigned long long)(unsigned)(w * 1048576.0f + 0.5f);
}

// SMEM half pitches
#define PA2 136
#define PBK 136
#define GSMEM ((128 * PA2 + 128 * PBK) * 2)       // 69.6 KB dyn -> 2 CTAs/SM

// ---------------- prep: zero packed/stats + weight fp16 transpose ----------------
__global__ void prep(unsigned long long* packed, float* stats,
                     const float* __restrict__ W0, const float* __restrict__ W1,
                     const float* __restrict__ W2, const float* __restrict__ W3,
                     __half* __restrict__ wt) {
    int i = blockIdx.x * blockDim.x + threadIdx.x;
    if (i < NN) packed[i] = 0ull;
    if (i < 512) stats[i] = 0.f;
    if (i < 65536) {
        const float* W = (i < 16384) ? W0 : (i < 32768) ? W1 : (i < 49152) ? W2 : W3;
        int j = i & 16383;
        int n = j >> 7, k = j & 127;
        wt[i] = __float2half(W[k * 128 + n]);
    }
}

// ---------------- A staging (256 threads) ----------------
__device__ __forceinline__ void stage_A_f32(const float* __restrict__ A, __half* As,
                                            int row0, int nrows, int tid) {
#pragma unroll
    for (int i = 0; i < 16; i++) {
        int f = i * 256 + tid;
        int row = f >> 5, kq = f & 31;
        float4 v = make_float4(0.f, 0.f, 0.f, 0.f);
        if (row0 + row < nrows)
            v = ((const float4*)A)[(size_t)(row0 + row) * 32 + kq];
        __half2 h0 = __floats2half2_rn(v.x, v.y);
        __half2 h1 = __floats2half2_rn(v.z, v.w);
        uint2 t; t.x = *(uint32_t*)&h0; t.y = *(uint32_t*)&h1;
        *(uint2*)&As[row * PA2 + kq * 4] = t;
    }
}
__device__ __forceinline__ void stage_A_f16(const __half* __restrict__ A,
                                            const float* affine,   // smem
                                            __half* As, int row0, int nrows, int tid) {
#pragma unroll
    for (int i = 0; i < 16; i++) {
        int f = i * 256 + tid;
        int row = f >> 5, kq = f & 31;
        uint2 q = make_uint2(0u, 0u);
        if (row0 + row < nrows)
            q = ((const uint2*)A)[(size_t)(row0 + row) * 32 + kq];
        float2 f01 = __half22float2(*(__half2*)&q.x);
        float2 f23 = __half22float2(*(__half2*)&q.y);
        int k0 = kq * 4;
        f01.x = f01.x * affine[k0 + 0] + affine[128 + k0 + 0];
        f01.y = f01.y * affine[k0 + 1] + affine[128 + k0 + 1];
        f23.x = f23.x * affine[k0 + 2] + affine[128 + k0 + 2];
        f23.y = f23.y * affine[k0 + 3] + affine[128 + k0 + 3];
        __half2 h0 = __floats2half2_rn(f01.x, f01.y);
        __half2 h1 = __floats2half2_rn(f23.x, f23.y);
        uint2 t; t.x = *(uint32_t*)&h0; t.y = *(uint32_t*)&h1;
        *(uint2*)&As[row * PA2 + kq * 4] = t;
    }
}

// ---------------- fp16 MMA mainloop: 8 k16-steps; A and B via ldmatrix ----------------
__device__ __forceinline__ void mma_loop_h(uint32_t abase, uint32_t bbase,
                                           float acc[4][4][4]) {
#pragma unroll
    for (int ks = 0; ks < 8; ks++) {
        uint32_t a[4][4];
#pragma unroll
        for (int mi = 0; mi < 4; mi++)
            ldsm4(a[mi], abase + (uint32_t)(mi * 16 * PA2 * 2 + ks * 32));
        uint32_t bv0[4], bv1[4];
        ldsm4(bv0, bbase + (uint32_t)(ks * 32));
        ldsm4(bv1, bbase + (uint32_t)(16 * PBK * 2 + ks * 32));
        uint32_t b[4][2];
        b[0][0] = bv0[0]; b[0][1] = bv0[1];
        b[1][0] = bv0[2]; b[1][1] = bv0[3];
        b[2][0] = bv1[0]; b[2][1] = bv1[1];
        b[3][0] = bv1[2]; b[3][1] = bv1[3];
#pragma unroll
        for (int mi = 0; mi < 4; mi++)
#pragma unroll
            for (int ni = 0; ni < 4; ni++)
                mma_f16(acc[mi][ni], a[mi], b[ni]);
    }
}

__device__ __forceinline__ uint32_t b_ldsm_base(const __half* Bs, int wn, int lane) {
    int brow = wn + ((lane >> 4) << 3) + (lane & 7);
    int bko  = ((lane >> 3) & 1) << 3;
    return smem_u32(Bs) + (uint32_t)((brow * PBK + bko) * 2);
}

// inline bn_finalize: raw sums -> scale/shift in smem aff[256]
__device__ __forceinline__ void compute_affine(float* aff, const float* __restrict__ rawstats,
                                               const float* __restrict__ gamma,
                                               const float* __restrict__ beta, int tid) {
    if (tid < 128) {
        float invn = 1.0f / (float)NN;
        float m = rawstats[tid] * invn;
        float var = rawstats[128 + tid] * invn - m * m;
        float sc = gamma[tid] * rsqrtf(var + EPSBN);
        aff[tid] = sc;
        aff[128 + tid] = beta[tid] - m * sc;
    }
}

// ---------------- GEMM: 256 threads, tile 128M x 128N, fp16 in/out ----------------
__global__ void __launch_bounds__(256) gemm_tc(const float* __restrict__ Af32,
                                               const __half* __restrict__ Ah,
                                               const __half* __restrict__ WT,
                                               const float* __restrict__ rawstats,
                                               const float* __restrict__ gamma,
                                               const float* __restrict__ beta,
                                               __half* __restrict__ out,
                                               int nrows) {
    extern __shared__ __half smemh[];
    __shared__ float aff[256];
    __half* As = smemh;
    __half* Bs = smemh + 128 * PA2;
    int tid = threadIdx.x, wid = tid >> 5, lane = tid & 31;
    int row0 = blockIdx.x * 128;
    int gid = lane >> 2, tg = lane & 3;
    int wm = (wid >> 2) * 64, wn = (wid & 3) * 32;

    uint32_t bbase = smem_u32(Bs);
#pragma unroll
    for (int i = 0; i < 8; i++) {
        int f = i * 256 + tid;
        int n = f >> 4, q = f & 15;
        cp_async16(bbase + (uint32_t)((n * PBK + q * 8) * 2),
                   WT + (size_t)n * 128 + q * 8);
    }
    asm volatile("cp.async.commit_group;");

    if (rawstats) {
        compute_affine(aff, rawstats, gamma, beta, tid);
        __syncthreads();
        stage_A_f16(Ah, aff, As, row0, nrows, tid);
    } else {
        stage_A_f32(Af32, As, row0, nrows, tid);
    }

    asm volatile("cp.async.wait_group 0;" ::: "memory");
    __syncthreads();

    int ldrow = wm + ((lane >> 3) & 1) * 8 + (lane & 7);
    uint32_t abase = smem_u32(As) + (uint32_t)(ldrow * PA2 * 2 + ((lane >> 4) << 4));
    uint32_t bb = b_ldsm_base(Bs, wn, lane);

    float acc[4][4][4];
#pragma unroll
    for (int mi = 0; mi < 4; mi++)
#pragma unroll
        for (int ni = 0; ni < 4; ni++)
#pragma unroll
            for (int j = 0; j < 4; j++) acc[mi][ni][j] = 0.f;

    mma_loop_h(abase, bb, acc);

#pragma unroll
    for (int mi = 0; mi < 4; mi++) {
        int r_lo = row0 + wm + mi * 16 + gid;
        int r_hi = r_lo + 8;
#pragma unroll
        for (int ni = 0; ni < 4; ni++) {
            int c = wn + ni * 8 + 2 * tg;
            __half2 p0 = __floats2half2_rn(acc[mi][ni][0], acc[mi][ni][1]);
            __half2 p1 = __floats2half2_rn(acc[mi][ni][2], acc[mi][ni][3]);
            if (r_lo < nrows) *(__half2*)(out + (size_t)r_lo * 128 + c) = p0;
            if (r_hi < nrows) *(__half2*)(out + (size_t)r_hi * 128 + c) = p1;
        }
    }
}

// ---------------- fused MLP head with single B buffer + inline BN finalize ----------------
__global__ void __launch_bounds__(256) mlp_fused(const __half* __restrict__ A,
                                                 const __half* __restrict__ W1T,
                                                 const __half* __restrict__ W2T,
                                                 const float* __restrict__ rawstats,
                                                 const float* __restrict__ gamma,
                                                 const float* __restrict__ beta,
                                                 const float* __restrict__ b1,
                                                 const float* __restrict__ b2,
                                                 float* __restrict__ out, int nrows) {
    extern __shared__ __half smemh[];
    __shared__ float aff[256];
    __half* As = smemh;
    __half* Bs = smemh + 128 * PA2;
    int tid = threadIdx.x, wid = tid >> 5, lane = tid & 31;
    int row0 = blockIdx.x * 128;
    int gid = lane >> 2, tg = lane & 3;
    int wm = (wid >> 2) * 64, wn = (wid & 3) * 32;

    uint32_t bbase = smem_u32(Bs);
#pragma unroll
    for (int i = 0; i < 8; i++) {
        int f = i * 256 + tid;
        int n = f >> 4, q = f & 15;
        cp_async16(bbase + (uint32_t)((n * PBK + q * 8) * 2), W1T + (size_t)n * 128 + q * 8);
    }
    asm volatile("cp.async.commit_group;");

    compute_affine(aff, rawstats, gamma, beta, tid);
    __syncthreads();
    stage_A_f16(A, aff, As, row0, nrows, tid);

    asm volatile("cp.async.wait_group 0;" ::: "memory");
    __syncthreads();

    int ldrow = wm + ((lane >> 3) & 1) * 8 + (lane & 7);
    uint32_t abase = smem_u32(As) + (uint32_t)(ldrow * PA2 * 2 + ((lane >> 4) << 4));
    uint32_t bb = b_ldsm_base(Bs, wn, lane);

    float acc[4][4][4];
#pragma unroll
    for (int mi = 0; mi < 4; mi++)
#pragma unroll
        for (int ni = 0; ni < 4; ni++)
#pragma unroll
            for (int j = 0; j < 4; j++) acc[mi][ni][j] = 0.f;

    mma_loop_h(abase, bb, acc);
    __syncthreads();   // all reads of Bs (W1) and As done

#pragma unroll
    for (int i = 0; i < 8; i++) {
        int f = i * 256 + tid;
        int n = f >> 4, q = f & 15;
        cp_async16(bbase + (uint32_t)((n * PBK + q * 8) * 2), W2T + (size_t)n * 128 + q * 8);
    }
    asm volatile("cp.async.commit_group;");

#pragma unroll
    for (int ni = 0; ni < 4; ni++) {
        int c = wn + ni * 8 + 2 * tg;
        float bx = b1[c], by = b1[c + 1];
#pragma unroll
        for (int mi = 0; mi < 4; mi++) {
            int r = wm + mi * 16 + gid;
            __half2 t0 = __floats2half2_rn(fmaxf(acc[mi][ni][0] + bx, 0.f),
                                           fmaxf(acc[mi][ni][1] + by, 0.f));
            __half2 t1 = __floats2half2_rn(fmaxf(acc[mi][ni][2] + bx, 0.f),
                                           fmaxf(acc[mi][ni][3] + by, 0.f));
            *(__half2*)&As[r * PA2 + c] = t0;
            *(__half2*)&As[(r + 8) * PA2 + c] = t1;
        }
    }
    asm volatile("cp.async.wait_group 0;" ::: "memory");
    __syncthreads();

#pragma unroll
    for (int mi = 0; mi < 4; mi++)
#pragma unroll
        for (int ni = 0; ni < 4; ni++)
#pragma unroll
            for (int j = 0; j < 4; j++) acc[mi][ni][j] = 0.f;

    mma_loop_h(abase, bb, acc);

    float2 bv[4];
#pragma unroll
    for (int ni = 0; ni < 4; ni++) {
        int c = wn + ni * 8 + 2 * tg;
        bv[ni].x = b2[c]; bv[ni].y = b2[c + 1];
    }
#pragma unroll
    for (int mi = 0; mi < 4; mi++) {
        int r_lo = row0 + wm + mi * 16 + gid;
        int r_hi = r_lo + 8;
#pragma unroll
        for (int ni = 0; ni < 4; ni++) {
            int c = wn + ni * 8 + 2 * tg;
            float2 v0, v1;
            v0.x = acc[mi][ni][0] + bv[ni].x;
            v0.y = acc[mi][ni][1] + bv[ni].y;
            v1.x = acc[mi][ni][2] + bv[ni].x;
            v1.y = acc[mi][ni][3] + bv[ni].y;
            if (r_lo < nrows) *(float2*)(out + (size_t)r_lo * 128 + c) = v0;
            if (r_hi < nrows) *(float2*)(out + (size_t)r_hi * 128 + c) = v1;
        }
    }
}

// ---------------- degree histogram: 4 edges per thread, one 64-bit atomic per edge -------
__global__ void hist_kernel(const int* __restrict__ dst, const float* __restrict__ attr,
                            unsigned long long* packed) {
    int i = blockIdx.x * blockDim.x + threadIdx.x;
    if (i >= EE / 4) return;
    int4 d4 = ((const int4*)dst)[i];
    float4 a0 = ((const float4*)attr)[2 * i];
    float4 a1 = ((const float4*)attr)[2 * i + 1];
    atomicAdd(&packed[d4.x], pack_w(a0.y));
    atomicAdd(&packed[d4.y], pack_w(a0.w));
    atomicAdd(&packed[d4.z], pack_w(a1.y));
    atomicAdd(&packed[d4.w], pack_w(a1.w));
}

// ---------------- scan (dinv computed from packed; cnt = hi32) ----------------
__global__ void scan1(const unsigned long long* __restrict__ in, int* __restrict__ out,
                      int* __restrict__ bsums, int n, float* dinv) {
    __shared__ int sh[256];
    int tid = threadIdx.x;
    int base = blockIdx.x * 1024;
    int v[4]; int tsum = 0;
#pragma unroll
    for (int j = 0; j < 4; j++) {
        int idx = base + tid * 4 + j;
        if (idx < n) {
            unsigned long long p = in[idx];
            v[j] = (int)(p >> 32);
            dinv[idx] = rsqrtf((float)(unsigned)p * (1.0f / 1048576.0f) + 1.0f);
        } else v[j] = 0;
        tsum += v[j];
    }
    sh[tid] = tsum; __syncthreads();
#pragma unroll
    for (int off = 1; off < 256; off <<= 1) {
        int t = (tid >= off) ? sh[tid - off] : 0;
        __syncthreads();
        sh[tid] += t;
        __syncthreads();
    }
    int run = sh[tid] - tsum;
#pragma unroll
    for (int j = 0; j < 4; j++) {
        int idx = base + tid * 4 + j;
        run += v[j];
        if (idx < n) out[idx] = run;
    }
    if (tid == 255) bsums[blockIdx.x] = sh[255];
}

__global__ void scan2(int* bs, int nb) {
    __shared__ int sh[128];
    int tid = threadIdx.x;
    int orig = (tid < nb) ? bs[tid] : 0;
    sh[tid] = orig; __syncthreads();
#pragma unroll
    for (int off = 1; off < 128; off <<= 1) {
        int t = (tid >= off) ? sh[tid - off] : 0;
        __syncthreads();
        sh[tid] += t;
        __syncthreads();
    }
    if (tid < nb) bs[tid] = sh[tid] - orig;
}

__global__ void scan3(int* out /* offs+1 */, const int* __restrict__ bs, int n,
                      int* offs0, int* cur) {
    int tid = threadIdx.x;
    int base = blockIdx.x * 1024;
    int add = bs[blockIdx.x];
#pragma unroll
    for (int j = 0; j < 4; j++) {
        int idx = base + tid * 4 + j;
        if (idx < n) {
            int v = out[idx] + add;
            out[idx] = v;
            if (idx + 1 < n) cur[idx + 1] = v;
        }
    }
    if (blockIdx.x == 0 && tid == 0) { offs0[0] = 0; cur[0] = 0; }
}

// ---------------- CSR fill: 4 edges per thread ----------------
__global__ void fill_kernel(const int* __restrict__ src, const int* __restrict__ dst,
                            const float* __restrict__ attr, const float* __restrict__ dinv,
                            int* cursor, int2* cpack) {
    int i = blockIdx.x * blockDim.x + threadIdx.x;
    if (i >= EE / 4) return;
    int4 s4 = ((const int4*)src)[i];
    int4 d4 = ((const int4*)dst)[i];
    float4 a0 = ((const float4*)attr)[2 * i];
    float4 a1 = ((const float4*)attr)[2 * i + 1];
    int p0 = atomicAdd(&cursor[d4.x], 1);
    int p1 = atomicAdd(&cursor[d4.y], 1);
    int p2 = atomicAdd(&cursor[d4.z], 1);
    int p3 = atomicAdd(&cursor[d4.w], 1);
    int2 q;
    q.x = s4.x; q.y = __float_as_int(dinv[s4.x] * a0.y * dinv[d4.x]); cpack[p0] = q;
    q.x = s4.y; q.y = __float_as_int(dinv[s4.y] * a0.w * dinv[d4.y]); cpack[p1] = q;
    q.x = s4.z; q.y = __float_as_int(dinv[s4.z] * a1.y * dinv[d4.z]); cpack[p2] = q;
    q.x = s4.w; q.y = __float_as_int(dinv[s4.w] * a1.w * dinv[d4.w]); cpack[p3] = q;
}

// ---------------- GCN aggregation + fused BN raw-sum stats ----------------
// HALF-WARP per node, 4 nodes per half-warp (grid-stride), uint4 gathers.
// BN sums accumulate in registers across nodes; ONE block reduction at kernel end.
#define AGB 1563                 // blocks
#define HWTOT (AGB * 16)         // 25008 half-warps
__global__ void __launch_bounds__(256) agg_kernel(const __half* __restrict__ hw,
                                                  const float* __restrict__ dinv,
                                                  const int* __restrict__ offs,
                                                  const int2* __restrict__ cpack,
                                                  const float* __restrict__ bias,
                                                  __half* __restrict__ out,
                                                  float* __restrict__ stats) {
    __shared__ float red[8][128];
    int tid = threadIdx.x;
    int lane = tid & 15;
    int wid = tid >> 5;
    int hw_id = (blockIdx.x << 4) + (tid >> 4);

    const uint4* feat = (const uint4*)hw;

    float4 b0 = ((const float4*)bias)[lane * 2];
    float4 b1 = ((const float4*)bias)[lane * 2 + 1];

    float bnS[8], bnQ[8];
#pragma unroll
    for (int j = 0; j < 8; j++) { bnS[j] = 0.f; bnQ[j] = 0.f; }

    for (int node = hw_id; node < NN; node += HWTOT) {
        float di = dinv[node];
        float self = di * di;
        float acc[8];
        {
            uint4 q = feat[(size_t)node * 16 + lane];
            float2 a = __half22float2(*(__half2*)&q.x);
            float2 b = __half22float2(*(((__half2*)&q.x) + 1));
            float2 c = __half22float2(*(__half2*)&q.z);
            float2 d = __half22float2(*(((__half2*)&q.z) + 1));
            acc[0] = self * a.x; acc[1] = self * a.y;
            acc[2] = self * b.x; acc[3] = self * b.y;
            acc[4] = self * c.x; acc[5] = self * c.y;
            acc[6] = self * d.x; acc[7] = self * d.y;
        }
        int p0 = offs[node], p1 = offs[node + 1];
#pragma unroll 4
        for (int p = p0; p < p1; p++) {
            int2 e = cpack[p];
            float c = __int_as_float(e.y);
            uint4 q = feat[(size_t)e.x * 16 + lane];
            float2 g0 = __half22float2(*(__half2*)&q.x);
            float2 g1 = __half22float2(*(((__half2*)&q.x) + 1));
            float2 g2 = __half22float2(*(__half2*)&q.z);
            float2 g3 = __half22float2(*(((__half2*)&q.z) + 1));
            acc[0] += c * g0.x; acc[1] += c * g0.y;
            acc[2] += c * g1.x; acc[3] += c * g1.y;
            acc[4] += c * g2.x; acc[5] += c * g2.y;
            acc[6] += c * g3.x; acc[7] += c * g3.y;
        }
        acc[0] = fmaxf(acc[0] + b0.x, 0.f); acc[1] = fmaxf(acc[1] + b0.y, 0.f);
        acc[2] = fmaxf(acc[2] + b0.z, 0.f); acc[3] = fmaxf(acc[3] + b0.w, 0.f);
        acc[4] = fmaxf(acc[4] + b1.x, 0.f); acc[5] = fmaxf(acc[5] + b1.y, 0.f);
        acc[6] = fmaxf(acc[6] + b1.z, 0.f); acc[7] = fmaxf(acc[7] + b1.w, 0.f);

#pragma unroll
        for (int j = 0; j < 8; j++) { bnS[j] += acc[j]; bnQ[j] += acc[j] * acc[j]; }

        __half2 h0 = __floats2half2_rn(acc[0], acc[1]);
        __half2 h1 = __floats2half2_rn(acc[2], acc[3]);
        __half2 h2 = __floats2half2_rn(acc[4], acc[5]);
        __half2 h3 = __floats2half2_rn(acc[6], acc[7]);
        uint4 o;
        o.x = *(uint32_t*)&h0; o.y = *(uint32_t*)&h1;
        o.z = *(uint32_t*)&h2; o.w = *(uint32_t*)&h3;
        ((uint4*)out)[(size_t)node * 16 + lane] = o;
    }

    // ---- end-of-kernel BN reduction (sums) ----
#pragma unroll
    for (int j = 0; j < 8; j++)
        bnS[j] += __shfl_down_sync(0xFFFFFFFFu, bnS[j], 16);
    if ((tid & 31) < 16) {
#pragma unroll
        for (int j = 0; j < 8; j++) red[wid][lane * 8 + j] = bnS[j];
    }
    __syncthreads();
    if (tid < 128) {
        float tot = 0.f;
#pragma unroll
        for (int w = 0; w < 8; w++) tot += red[w][tid];
        atomicAdd(&stats[tid], tot);
    }
    __syncthreads();
    // ---- sums of squares ----
#pragma unroll
    for (int j = 0; j < 8; j++)
        bnQ[j] += __shfl_down_sync(0xFFFFFFFFu, bnQ[j], 16);
    if ((tid & 31) < 16) {
#pragma unroll
        for (int j = 0; j < 8; j++) red[wid][lane * 8 + j] = bnQ[j];
    }
    __syncthreads();
    if (tid < 128) {
        float tot = 0.f;
#pragma unroll
        for (int w = 0; w < 8; w++) tot += red[w][tid];
        atomicAdd(&stats[128 + tid], tot);
    }
}

// ---------------- pooling: 8 partial blocks per group ----------------
__global__ void pool_partial(const float* __restrict__ h, const int* __restrict__ batch,
                             float* __restrict__ part, float* __restrict__ pcnt) {
    int g = blockIdx.x >> 3, c = blockIdx.x & 7;
    int lo = 0, hi = NN;
    while (lo < hi) { int mid = (lo + hi) >> 1; if (batch[mid] < g) lo = mid + 1; else hi = mid; }
    int start = lo;
    lo = start; hi = NN;
    while (lo < hi) { int mid = (lo + hi) >> 1; if (batch[mid] < g + 1) lo = mid + 1; else hi = mid; }
    int end = lo;
    int len = end - start;
    int b0 = start + (int)(((long long)len * c) >> 3);
    int b1 = start + (int)(((long long)len * (c + 1)) >> 3);
    int d = threadIdx.x;
    float s = 0.f;
    for (int r = b0; r < b1; r++) s += h[(size_t)r * 128 + d];
    part[(g * 8 + c) * 128 + d] = s;
    if (c == 0 && d == 0) pcnt[g] = (float)len;
}

// ---------------- classifier: one block per group ----------------
__global__ void classify_kernel(const float* __restrict__ part, const float* __restrict__ pcnt,
                                float* __restrict__ reps,
                                const float* __restrict__ Wc1, const float* __restrict__ bc1,
                                const float* __restrict__ Wc2, const float* __restrict__ bc2,
                                float* __restrict__ logits) {
    __shared__ float rsh[128];
    __shared__ float tsh[128];
    int g = blockIdx.x;
    int d = threadIdx.x;
    float s = 0.f;
#pragma unroll
    for (int c = 0; c < 8; c++) s += part[(g * 8 + c) * 128 + d];
    float inv = 1.0f / fmaxf(pcnt[g], 1.0f);
    float rv = s * inv;
    reps[g * 128 + d] = rv;
    rsh[d] = rv;
    __syncthreads();
    float t = bc1[d];
#pragma unroll
    for (int k = 0; k < 128; k++) t += rsh[k] * Wc1[k * 128 + d];
    tsh[d] = fmaxf(t, 0.f);
    __syncthreads();
    if (d < CC) {
        float s2 = bc2[d];
#pragma unroll
        for (int k = 0; k < 128; k++) s2 += tsh[k] * Wc2[k * CC + d];
        logits[g * CC + d] = s2;
    }
}

// ---------------- launch ----------------
extern "C" void kernel_launch(void* const* d_in, const int* in_sizes, int n_in,
                              void* d_out, int out_size) {
    const float* x     = (const float*)d_in[0];
    const int*   ei    = (const int*)d_in[1];
    const float* ea    = (const float*)d_in[2];
    const int*   batch = (const int*)d_in[3];
    const float* Wg0 = (const float*)d_in[4],  *bg0 = (const float*)d_in[5];
    const float* gamma0 = (const float*)d_in[6], *beta0 = (const float*)d_in[7];
    const float* Wg1 = (const float*)d_in[8],  *bg1 = (const float*)d_in[9];
    const float* gamma1 = (const float*)d_in[10], *beta1 = (const float*)d_in[11];
    const float* Wl1 = (const float*)d_in[12], *bl1 = (const float*)d_in[13];
    const float* Wl2 = (const float*)d_in[14], *bl2 = (const float*)d_in[15];
    const float* Wc1 = (const float*)d_in[16], *bc1 = (const float*)d_in[17];
    const float* Wc2 = (const float*)d_in[18], *bc2 = (const float*)d_in[19];

    float* out = (float*)d_out;
    float* h_out  = out;
    float* reps   = out + (size_t)NN * DD;
    float* logits = out + (size_t)NN * DD + (size_t)GG * DD;

    float *dinv, *stats, *pool, *pcnt;
    __half *bufAh, *bufBh, *wt;
    unsigned long long *packed;
    int *offs, *cur, *bsums;
    int2 *cpack;
    cudaGetSymbolAddress((void**)&bufAh, g_bufA);
    cudaGetSymbolAddress((void**)&bufBh, g_bufB);
    cudaGetSymbolAddress((void**)&dinv, g_dinv);
    cudaGetSymbolAddress((void**)&packed, g_packed);
    cudaGetSymbolAddress((void**)&offs, g_offs);
    cudaGetSymbolAddress((void**)&cur, g_cursor);
    cudaGetSymbolAddress((void**)&bsums, g_bsums);
    cudaGetSymbolAddress((void**)&cpack, g_cpack);
    cudaGetSymbolAddress((void**)&stats, g_stats);
    cudaGetSymbolAddress((void**)&pool, g_pool);
    cudaGetSymbolAddress((void**)&pcnt, g_pcnt);
    cudaGetSymbolAddress((void**)&wt, g_wt);

    float* stats0 = stats;
    float* stats1 = stats + 256;

    cudaFuncSetAttribute(gemm_tc, cudaFuncAttributeMaxDynamicSharedMemorySize, GSMEM);
    cudaFuncSetAttribute(mlp_fused, cudaFuncAttributeMaxDynamicSharedMemorySize, GSMEM);

    const int* src = ei;
    const int* dst = ei + EE;

    const int TB = 256;
    const int gridE4 = (EE / 4 + TB - 1) / TB;      // 1563
    const int gridG  = (NN + 127) / 128;            // 782
    const int nScanB = (NN + 1023) / 1024;

    // side stream for CSR build (created per call; not destroyed — capture-safe)
    cudaStream_t sB;
    cudaStreamCreateWithFlags(&sB, cudaStreamNonBlocking);
    cudaEvent_t eFork, eJoin;
    cudaEventCreateWithFlags(&eFork, cudaEventDisableTiming);
    cudaEventCreateWithFlags(&eJoin, cudaEventDisableTiming);

    // prep on main stream, then fork
    prep<<<(NN + TB - 1) / TB, TB>>>(packed, stats, Wg0, Wg1, Wl1, Wl2, wt);
    cudaEventRecord(eFork, 0);
    cudaStreamWaitEvent(sB, eFork, 0);

    // branch B (side stream): CSR build
    hist_kernel<<<gridE4, TB, 0, sB>>>(dst, ea, packed);
    scan1<<<nScanB, 256, 0, sB>>>(packed, offs + 1, bsums, NN, dinv);
    scan2<<<1, 128, 0, sB>>>(bsums, nScanB);
    scan3<<<nScanB, 256, 0, sB>>>(offs + 1, bsums, NN, offs, cur);
    fill_kernel<<<gridE4, TB, 0, sB>>>(src, dst, ea, dinv, cur, cpack);
    cudaEventRecord(eJoin, sB);

    // branch A (main stream): layer-0 GEMM
    gemm_tc<<<gridG, 256, GSMEM>>>(x, nullptr, wt + 0 * 16384, nullptr, nullptr, nullptr, bufAh, NN);

    // join
    cudaStreamWaitEvent(0, eJoin, 0);

    // GCN layer 0 (agg accumulates BN raw sums into stats0)
    agg_kernel<<<AGB, 256>>>(bufAh, dinv, offs, cpack, bg0, bufBh, stats0);

    // GCN layer 1 (bn0 finalize+affine fused into GEMM A-load; agg -> stats1)
    gemm_tc<<<gridG, 256, GSMEM>>>(nullptr, bufBh, wt + 1 * 16384, stats0, gamma0, beta0, bufAh, NN);
    agg_kernel<<<AGB, 256>>>(bufAh, dinv, offs, cpack, bg1, bufBh, stats1);

    // fused MLP head (bn1 finalize+affine fused into A-load)
    mlp_fused<<<gridG, 256, GSMEM>>>(bufBh, wt + 2 * 16384, wt + 3 * 16384,
                                     stats1, gamma1, beta1, bl1, bl2, h_out, NN);

    // pooling + classifier
    pool_partial<<<GG * 8, 128>>>(h_out, batch, pool, pcnt);
    classify_kernel<<<GG, 128>>>(pool, pcnt, reps, Wc1, bc1, Wc2, bc2, logits);
}

// round 16
// speedup vs baseline: 1.0888x; 1.0888x over previous
#include <cuda_runtime.h>
#include <cuda_fp16.h>
#include <cstdint>

#define NN 100000
#define EE 1600000
#define DD 128
#define GG 64
#define CC 2
#define EPSBN 1e-5f

// ---------------- scratch (static device globals; no allocation) ----------------
__device__ __half g_bufA[(size_t)NN * DD];
__device__ __half g_bufB[(size_t)NN * DD];
__device__ float g_dinv[NN];
__device__ unsigned long long g_packed[NN];   // hi32: count, lo32: fixed-point weight sum
__device__ int   g_offs[NN + 1];
__device__ int   g_cursor[NN];
__device__ int   g_bsums[512];
__device__ int2  g_cpack[EE];
__device__ float g_stats[512];          // [0:256) layer0 raw sums, [256:512) layer1
__device__ float g_pool[GG * 16 * DD];
__device__ float g_pcnt[GG];
__device__ __half g_wt[4 * 128 * 128];  // fp16 weights, TRANSPOSED: [n][k]

// ---------------- helpers ----------------
__device__ __forceinline__ uint32_t smem_u32(const void* p) {
    uint32_t a;
    asm("{ .reg .u64 t; cvta.to.shared.u64 t, %1; cvt.u32.u64 %0, t; }" : "=r"(a) : "l"(p));
    return a;
}
__device__ __forceinline__ void mma_f16(float* d, const uint32_t* a, const uint32_t* b) {
    asm volatile(
        "mma.sync.aligned.m16n8k16.row.col.f32.f16.f16.f32 "
        "{%0,%1,%2,%3}, {%4,%5,%6,%7}, {%8,%9}, {%0,%1,%2,%3};"
        : "+f"(d[0]), "+f"(d[1]), "+f"(d[2]), "+f"(d[3])
        : "r"(a[0]), "r"(a[1]), "r"(a[2]), "r"(a[3]), "r"(b[0]), "r"(b[1]));
}
__device__ __forceinline__ void ldsm4(uint32_t* a, uint32_t addr) {
    asm volatile("ldmatrix.sync.aligned.m8n8.x4.shared.b16 {%0,%1,%2,%3}, [%4];"
        : "=r"(a[0]), "=r"(a[1]), "=r"(a[2]), "=r"(a[3]) : "r"(addr));
}
__device__ __forceinline__ void cp_async16(uint32_t saddr, const void* gaddr) {
    asm volatile("cp.async.cg.shared.global [%0], [%1], 16;" :: "r"(saddr), "l"(gaddr));
}
__device__ __forceinline__ unsigned long long pack_w(float w) {
    return (1ull << 32) | (unsigned long long)(unsigned)(w * 1048576.0f + 0.5f);
}

// SMEM half pitches
#define PA2 136
#define PBK 136
#define GSMEM ((128 * PA2 + 128 * PBK) * 2)       // 69.6 KB dyn -> 2 CTAs/SM

// ---------------- prep: zero packed/stats + weight fp16 transpose ----------------
__global__ void prep(unsigned long long* packed, float* stats,
                     const float* __restrict__ W0, const float* __restrict__ W1,
                     const float* __restrict__ W2, const float* __restrict__ W3,
                     __half* __restrict__ wt) {
    int i = blockIdx.x * blockDim.x + threadIdx.x;
    if (i < NN) packed[i] = 0ull;
    if (i < 512) stats[i] = 0.f;
    if (i < 65536) {
        const float* W = (i < 16384) ? W0 : (i < 32768) ? W1 : (i < 49152) ? W2 : W3;
        int j = i & 16383;
        int n = j >> 7, k = j & 127;
        wt[i] = __float2half(W[k * 128 + n]);
    }
}

// ---------------- A staging (256 threads) ----------------
__device__ __forceinline__ void stage_A_f32(const float* __restrict__ A, __half* As,
                                            int row0, int nrows, int tid) {
#pragma unroll
    for (int i = 0; i < 16; i++) {
        int f = i * 256 + tid;
        int row = f >> 5, kq = f & 31;
        float4 v = make_float4(0.f, 0.f, 0.f, 0.f);
        if (row0 + row < nrows)
            v = ((const float4*)A)[(size_t)(row0 + row) * 32 + kq];
        __half2 h0 = __floats2half2_rn(v.x, v.y);
        __half2 h1 = __floats2half2_rn(v.z, v.w);
        uint2 t; t.x = *(uint32_t*)&h0; t.y = *(uint32_t*)&h1;
        *(uint2*)&As[row * PA2 + kq * 4] = t;
    }
}
__device__ __forceinline__ void stage_A_f16(const __half* __restrict__ A,
                                            const float* affine,   // smem
                                            __half* As, int row0, int nrows, int tid) {
#pragma unroll
    for (int i = 0; i < 16; i++) {
        int f = i * 256 + tid;
        int row = f >> 5, kq = f & 31;
        uint2 q = make_uint2(0u, 0u);
        if (row0 + row < nrows)
            q = ((const uint2*)A)[(size_t)(row0 + row) * 32 + kq];
        float2 f01 = __half22float2(*(__half2*)&q.x);
        float2 f23 = __half22float2(*(__half2*)&q.y);
        int k0 = kq * 4;
        f01.x = f01.x * affine[k0 + 0] + affine[128 + k0 + 0];
        f01.y = f01.y * affine[k0 + 1] + affine[128 + k0 + 1];
        f23.x = f23.x * affine[k0 + 2] + affine[128 + k0 + 2];
        f23.y = f23.y * affine[k0 + 3] + affine[128 + k0 + 3];
        __half2 h0 = __floats2half2_rn(f01.x, f01.y);
        __half2 h1 = __floats2half2_rn(f23.x, f23.y);
        uint2 t; t.x = *(uint32_t*)&h0; t.y = *(uint32_t*)&h1;
        *(uint2*)&As[row * PA2 + kq * 4] = t;
    }
}

// ---------------- fp16 MMA mainloop: 8 k16-steps; A and B via ldmatrix ----------------
__device__ __forceinline__ void mma_loop_h(uint32_t abase, uint32_t bbase,
                                           float acc[4][4][4]) {
#pragma unroll
    for (int ks = 0; ks < 8; ks++) {
        uint32_t a[4][4];
#pragma unroll
        for (int mi = 0; mi < 4; mi++)
            ldsm4(a[mi], abase + (uint32_t)(mi * 16 * PA2 * 2 + ks * 32));
        uint32_t bv0[4], bv1[4];
        ldsm4(bv0, bbase + (uint32_t)(ks * 32));
        ldsm4(bv1, bbase + (uint32_t)(16 * PBK * 2 + ks * 32));
        uint32_t b[4][2];
        b[0][0] = bv0[0]; b[0][1] = bv0[1];
        b[1][0] = bv0[2]; b[1][1] = bv0[3];
        b[2][0] = bv1[0]; b[2][1] = bv1[1];
        b[3][0] = bv1[2]; b[3][1] = bv1[3];
#pragma unroll
        for (int mi = 0; mi < 4; mi++)
#pragma unroll
            for (int ni = 0; ni < 4; ni++)
                mma_f16(acc[mi][ni], a[mi], b[ni]);
    }
}

__device__ __forceinline__ uint32_t b_ldsm_base(const __half* Bs, int wn, int lane) {
    int brow = wn + ((lane >> 4) << 3) + (lane & 7);
    int bko  = ((lane >> 3) & 1) << 3;
    return smem_u32(Bs) + (uint32_t)((brow * PBK + bko) * 2);
}

// inline bn_finalize: raw sums -> scale/shift in smem aff[256]
__device__ __forceinline__ void compute_affine(float* aff, const float* __restrict__ rawstats,
                                               const float* __restrict__ gamma,
                                               const float* __restrict__ beta, int tid) {
    if (tid < 128) {
        float invn = 1.0f / (float)NN;
        float m = rawstats[tid] * invn;
        float var = rawstats[128 + tid] * invn - m * m;
        float sc = gamma[tid] * rsqrtf(var + EPSBN);
        aff[tid] = sc;
        aff[128 + tid] = beta[tid] - m * sc;
    }
}

// ---------------- GEMM: 256 threads, tile 128M x 128N, fp16 in/out ----------------
__global__ void __launch_bounds__(256) gemm_tc(const float* __restrict__ Af32,
                                               const __half* __restrict__ Ah,
                                               const __half* __restrict__ WT,
                                               const float* __restrict__ rawstats,
                                               const float* __restrict__ gamma,
                                               const float* __restrict__ beta,
                                               __half* __restrict__ out,
                                               int nrows) {
    extern __shared__ __half smemh[];
    __shared__ float aff[256];
    __half* As = smemh;
    __half* Bs = smemh + 128 * PA2;
    int tid = threadIdx.x, wid = tid >> 5, lane = tid & 31;
    int row0 = blockIdx.x * 128;
    int gid = lane >> 2, tg = lane & 3;
    int wm = (wid >> 2) * 64, wn = (wid & 3) * 32;

    uint32_t bbase = smem_u32(Bs);
#pragma unroll
    for (int i = 0; i < 8; i++) {
        int f = i * 256 + tid;
        int n = f >> 4, q = f & 15;
        cp_async16(bbase + (uint32_t)((n * PBK + q * 8) * 2),
                   WT + (size_t)n * 128 + q * 8);
    }
    asm volatile("cp.async.commit_group;");

    if (rawstats) {
        compute_affine(aff, rawstats, gamma, beta, tid);
        __syncthreads();
        stage_A_f16(Ah, aff, As, row0, nrows, tid);
    } else {
        stage_A_f32(Af32, As, row0, nrows, tid);
    }

    asm volatile("cp.async.wait_group 0;" ::: "memory");
    __syncthreads();

    int ldrow = wm + ((lane >> 3) & 1) * 8 + (lane & 7);
    uint32_t abase = smem_u32(As) + (uint32_t)(ldrow * PA2 * 2 + ((lane >> 4) << 4));
    uint32_t bb = b_ldsm_base(Bs, wn, lane);

    float acc[4][4][4];
#pragma unroll
    for (int mi = 0; mi < 4; mi++)
#pragma unroll
        for (int ni = 0; ni < 4; ni++)
#pragma unroll
            for (int j = 0; j < 4; j++) acc[mi][ni][j] = 0.f;

    mma_loop_h(abase, bb, acc);

#pragma unroll
    for (int mi = 0; mi < 4; mi++) {
        int r_lo = row0 + wm + mi * 16 + gid;
        int r_hi = r_lo + 8;
#pragma unroll
        for (int ni = 0; ni < 4; ni++) {
            int c = wn + ni * 8 + 2 * tg;
            __half2 p0 = __floats2half2_rn(acc[mi][ni][0], acc[mi][ni][1]);
            __half2 p1 = __floats2half2_rn(acc[mi][ni][2], acc[mi][ni][3]);
            if (r_lo < nrows) *(__half2*)(out + (size_t)r_lo * 128 + c) = p0;
            if (r_hi < nrows) *(__half2*)(out + (size_t)r_hi * 128 + c) = p1;
        }
    }
}

// ---------------- fused MLP head with single B buffer + inline BN finalize ----------------
__global__ void __launch_bounds__(256) mlp_fused(const __half* __restrict__ A,
                                                 const __half* __restrict__ W1T,
                                                 const __half* __restrict__ W2T,
                                                 const float* __restrict__ rawstats,
                                                 const float* __restrict__ gamma,
                                                 const float* __restrict__ beta,
                                                 const float* __restrict__ b1,
                                                 const float* __restrict__ b2,
                                                 float* __restrict__ out, int nrows) {
    extern __shared__ __half smemh[];
    __shared__ float aff[256];
    __half* As = smemh;
    __half* Bs = smemh + 128 * PA2;
    int tid = threadIdx.x, wid = tid >> 5, lane = tid & 31;
    int row0 = blockIdx.x * 128;
    int gid = lane >> 2, tg = lane & 3;
    int wm = (wid >> 2) * 64, wn = (wid & 3) * 32;

    uint32_t bbase = smem_u32(Bs);
#pragma unroll
    for (int i = 0; i < 8; i++) {
        int f = i * 256 + tid;
        int n = f >> 4, q = f & 15;
        cp_async16(bbase + (uint32_t)((n * PBK + q * 8) * 2), W1T + (size_t)n * 128 + q * 8);
    }
    asm volatile("cp.async.commit_group;");

    compute_affine(aff, rawstats, gamma, beta, tid);
    __syncthreads();
    stage_A_f16(A, aff, As, row0, nrows, tid);

    asm volatile("cp.async.wait_group 0;" ::: "memory");
    __syncthreads();

    int ldrow = wm + ((lane >> 3) & 1) * 8 + (lane & 7);
    uint32_t abase = smem_u32(As) + (uint32_t)(ldrow * PA2 * 2 + ((lane >> 4) << 4));
    uint32_t bb = b_ldsm_base(Bs, wn, lane);

    float acc[4][4][4];
#pragma unroll
    for (int mi = 0; mi < 4; mi++)
#pragma unroll
        for (int ni = 0; ni < 4; ni++)
#pragma unroll
            for (int j = 0; j < 4; j++) acc[mi][ni][j] = 0.f;

    mma_loop_h(abase, bb, acc);
    __syncthreads();   // all reads of Bs (W1) and As done

#pragma unroll
    for (int i = 0; i < 8; i++) {
        int f = i * 256 + tid;
        int n = f >> 4, q = f & 15;
        cp_async16(bbase + (uint32_t)((n * PBK + q * 8) * 2), W2T + (size_t)n * 128 + q * 8);
    }
    asm volatile("cp.async.commit_group;");

#pragma unroll
    for (int ni = 0; ni < 4; ni++) {
        int c = wn + ni * 8 + 2 * tg;
        float bx = b1[c], by = b1[c + 1];
#pragma unroll
        for (int mi = 0; mi < 4; mi++) {
            int r = wm + mi * 16 + gid;
            __half2 t0 = __floats2half2_rn(fmaxf(acc[mi][ni][0] + bx, 0.f),
                                           fmaxf(acc[mi][ni][1] + by, 0.f));
            __half2 t1 = __floats2half2_rn(fmaxf(acc[mi][ni][2] + bx, 0.f),
                                           fmaxf(acc[mi][ni][3] + by, 0.f));
            *(__half2*)&As[r * PA2 + c] = t0;
            *(__half2*)&As[(r + 8) * PA2 + c] = t1;
        }
    }
    asm volatile("cp.async.wait_group 0;" ::: "memory");
    __syncthreads();

#pragma unroll
    for (int mi = 0; mi < 4; mi++)
#pragma unroll
        for (int ni = 0; ni < 4; ni++)
#pragma unroll
            for (int j = 0; j < 4; j++) acc[mi][ni][j] = 0.f;

    mma_loop_h(abase, bb, acc);

    float2 bv[4];
#pragma unroll
    for (int ni = 0; ni < 4; ni++) {
        int c = wn + ni * 8 + 2 * tg;
        bv[ni].x = b2[c]; bv[ni].y = b2[c + 1];
    }
#pragma unroll
    for (int mi = 0; mi < 4; mi++) {
        int r_lo = row0 + wm + mi * 16 + gid;
        int r_hi = r_lo + 8;
#pragma unroll
        for (int ni = 0; ni < 4; ni++) {
            int c = wn + ni * 8 + 2 * tg;
            float2 v0, v1;
            v0.x = acc[mi][ni][0] + bv[ni].x;
            v0.y = acc[mi][ni][1] + bv[ni].y;
            v1.x = acc[mi][ni][2] + bv[ni].x;
            v1.y = acc[mi][ni][3] + bv[ni].y;
            if (r_lo < nrows) *(float2*)(out + (size_t)r_lo * 128 + c) = v0;
            if (r_hi < nrows) *(float2*)(out + (size_t)r_hi * 128 + c) = v1;
        }
    }
}

// ---------------- degree histogram: 4 edges per thread, one 64-bit atomic per edge -------
__global__ void hist_kernel(const int* __restrict__ dst, const float* __restrict__ attr,
                            unsigned long long* packed) {
    int i = blockIdx.x * blockDim.x + threadIdx.x;
    if (i >= EE / 4) return;
    int4 d4 = ((const int4*)dst)[i];
    float4 a0 = ((const float4*)attr)[2 * i];
    float4 a1 = ((const float4*)attr)[2 * i + 1];
    atomicAdd(&packed[d4.x], pack_w(a0.y));
    atomicAdd(&packed[d4.y], pack_w(a0.w));
    atomicAdd(&packed[d4.z], pack_w(a1.y));
    atomicAdd(&packed[d4.w], pack_w(a1.w));
}

// ---------------- scan (dinv computed from packed; cnt = hi32) ----------------
__global__ void scan1(const unsigned long long* __restrict__ in, int* __restrict__ out,
                      int* __restrict__ bsums, int n, float* dinv) {
    __shared__ int sh[256];
    int tid = threadIdx.x;
    int base = blockIdx.x * 1024;
    int v[4]; int tsum = 0;
#pragma unroll
    for (int j = 0; j < 4; j++) {
        int idx = base + tid * 4 + j;
        if (idx < n) {
            unsigned long long p = in[idx];
            v[j] = (int)(p >> 32);
            dinv[idx] = rsqrtf((float)(unsigned)p * (1.0f / 1048576.0f) + 1.0f);
        } else v[j] = 0;
        tsum += v[j];
    }
    sh[tid] = tsum; __syncthreads();
#pragma unroll
    for (int off = 1; off < 256; off <<= 1) {
        int t = (tid >= off) ? sh[tid - off] : 0;
        __syncthreads();
        sh[tid] += t;
        __syncthreads();
    }
    int run = sh[tid] - tsum;
#pragma unroll
    for (int j = 0; j < 4; j++) {
        int idx = base + tid * 4 + j;
        run += v[j];
        if (idx < n) out[idx] = run;
    }
    if (tid == 255) bsums[blockIdx.x] = sh[255];
}

__global__ void scan2(int* bs, int nb) {
    __shared__ int sh[128];
    int tid = threadIdx.x;
    int orig = (tid < nb) ? bs[tid] : 0;
    sh[tid] = orig; __syncthreads();
#pragma unroll
    for (int off = 1; off < 128; off <<= 1) {
        int t = (tid >= off) ? sh[tid - off] : 0;
        __syncthreads();
        sh[tid] += t;
        __syncthreads();
    }
    if (tid < nb) bs[tid] = sh[tid] - orig;
}

__global__ void scan3(int* out /* offs+1 */, const int* __restrict__ bs, int n,
                      int* offs0, int* cur) {
    int tid = threadIdx.x;
    int base = blockIdx.x * 1024;
    int add = bs[blockIdx.x];
#pragma unroll
    for (int j = 0; j < 4; j++) {
        int idx = base + tid * 4 + j;
        if (idx < n) {
            int v = out[idx] + add;
            out[idx] = v;
            if (idx + 1 < n) cur[idx + 1] = v;
        }
    }
    if (blockIdx.x == 0 && tid == 0) { offs0[0] = 0; cur[0] = 0; }
}

// ---------------- CSR fill: 4 edges per thread ----------------
__global__ void fill_kernel(const int* __restrict__ src, const int* __restrict__ dst,
                            const float* __restrict__ attr, const float* __restrict__ dinv,
                            int* cursor, int2* cpack) {
    int i = blockIdx.x * blockDim.x + threadIdx.x;
    if (i >= EE / 4) return;
    int4 s4 = ((const int4*)src)[i];
    int4 d4 = ((const int4*)dst)[i];
    float4 a0 = ((const float4*)attr)[2 * i];
    float4 a1 = ((const float4*)attr)[2 * i + 1];
    int p0 = atomicAdd(&cursor[d4.x], 1);
    int p1 = atomicAdd(&cursor[d4.y], 1);
    int p2 = atomicAdd(&cursor[d4.z], 1);
    int p3 = atomicAdd(&cursor[d4.w], 1);
    int2 q;
    q.x = s4.x; q.y = __float_as_int(dinv[s4.x] * a0.y * dinv[d4.x]); cpack[p0] = q;
    q.x = s4.y; q.y = __float_as_int(dinv[s4.y] * a0.w * dinv[d4.y]); cpack[p1] = q;
    q.x = s4.z; q.y = __float_as_int(dinv[s4.z] * a1.y * dinv[d4.z]); cpack[p2] = q;
    q.x = s4.w; q.y = __float_as_int(dinv[s4.w] * a1.w * dinv[d4.w]); cpack[p3] = q;
}

// ---------------- GCN aggregation: HALF-WARP per node, uint4 gathers ----------------
__global__ void agg_kernel(const __half* __restrict__ hw, const float* __restrict__ dinv,
                           const int* __restrict__ offs, const int2* __restrict__ cpack,
                           const float* __restrict__ bias, __half* __restrict__ out) {
    int gtid = blockIdx.x * blockDim.x + threadIdx.x;
    int node = gtid >> 4;
    if (node >= NN) return;
    int lane = threadIdx.x & 15;

    const uint4* feat = (const uint4*)hw;

    float di = dinv[node];
    float self = di * di;
    float acc[8];
    {
        uint4 q = feat[(size_t)node * 16 + lane];
        float2 a = __half22float2(*(__half2*)&q.x);
        float2 b = __half22float2(*(((__half2*)&q.x) + 1));
        float2 c = __half22float2(*(__half2*)&q.z);
        float2 d = __half22float2(*(((__half2*)&q.z) + 1));
        acc[0] = self * a.x; acc[1] = self * a.y;
        acc[2] = self * b.x; acc[3] = self * b.y;
        acc[4] = self * c.x; acc[5] = self * c.y;
        acc[6] = self * d.x; acc[7] = self * d.y;
    }

    int p0 = offs[node], p1 = offs[node + 1];
#pragma unroll 4
    for (int p = p0; p < p1; p++) {
        int2 e = cpack[p];
        float c = __int_as_float(e.y);
        uint4 q = feat[(size_t)e.x * 16 + lane];
        float2 g0 = __half22float2(*(__half2*)&q.x);
        float2 g1 = __half22float2(*(((__half2*)&q.x) + 1));
        float2 g2 = __half22float2(*(__half2*)&q.z);
        float2 g3 = __half22float2(*(((__half2*)&q.z) + 1));
        acc[0] += c * g0.x; acc[1] += c * g0.y;
        acc[2] += c * g1.x; acc[3] += c * g1.y;
        acc[4] += c * g2.x; acc[5] += c * g2.y;
        acc[6] += c * g3.x; acc[7] += c * g3.y;
    }

    float4 b0 = ((const float4*)bias)[lane * 2];
    float4 b1 = ((const float4*)bias)[lane * 2 + 1];
    __half2 h0 = __floats2half2_rn(fmaxf(acc[0] + b0.x, 0.f), fmaxf(acc[1] + b0.y, 0.f));
    __half2 h1 = __floats2half2_rn(fmaxf(acc[2] + b0.z, 0.f), fmaxf(acc[3] + b0.w, 0.f));
    __half2 h2 = __floats2half2_rn(fmaxf(acc[4] + b1.x, 0.f), fmaxf(acc[5] + b1.y, 0.f));
    __half2 h3 = __floats2half2_rn(fmaxf(acc[6] + b1.z, 0.f), fmaxf(acc[7] + b1.w, 0.f));
    uint4 o;
    o.x = *(uint32_t*)&h0; o.y = *(uint32_t*)&h1;
    o.z = *(uint32_t*)&h2; o.w = *(uint32_t*)&h3;
    ((uint4*)out)[(size_t)node * 16 + lane] = o;
}

// ---------------- BatchNorm stats (vectorized uint4 loads) ----------------
#define BNBLK 296
#define BNCHUNK 338
__global__ void bn_stats(const __half* __restrict__ X, float* stats, int nrows) {
    __shared__ float red[16][128];
    int tid = threadIdx.x;
    int dc = tid & 15;        // dim chunk: dims dc*8 .. dc*8+7
    int rg = tid >> 4;        // row stream 0..15
    int r0 = blockIdx.x * BNCHUNK;
    int rend = min(r0 + BNCHUNK, nrows);

    float s[8], q[8];
#pragma unroll
    for (int j = 0; j < 8; j++) { s[j] = 0.f; q[j] = 0.f; }

    const uint4* Xv = (const uint4*)X;
    for (int r = r0 + rg; r < rend; r += 16) {
        uint4 u = Xv[(size_t)r * 16 + dc];
        float2 f0 = __half22float2(*(__half2*)&u.x);
        float2 f1 = __half22float2(*(((__half2*)&u.x) + 1));
        float2 f2 = __half22float2(*(__half2*)&u.z);
        float2 f3 = __half22float2(*(((__half2*)&u.z) + 1));
        float v0 = f0.x, v1 = f0.y, v2 = f1.x, v3 = f1.y;
        float v4 = f2.x, v5 = f2.y, v6 = f3.x, v7 = f3.y;
        s[0] += v0; q[0] += v0 * v0;  s[1] += v1; q[1] += v1 * v1;
        s[2] += v2; q[2] += v2 * v2;  s[3] += v3; q[3] += v3 * v3;
        s[4] += v4; q[4] += v4 * v4;  s[5] += v5; q[5] += v5 * v5;
        s[6] += v6; q[6] += v6 * v6;  s[7] += v7; q[7] += v7 * v7;
    }
#pragma unroll
    for (int j = 0; j < 8; j++) red[rg][dc * 8 + j] = s[j];
    __syncthreads();
    if (tid < 128) {
        float tot = 0.f;
#pragma unroll
        for (int g = 0; g < 16; g++) tot += red[g][tid];
        atomicAdd(&stats[tid], tot);
    }
    __syncthreads();
#pragma unroll
    for (int j = 0; j < 8; j++) red[rg][dc * 8 + j] = q[j];
    __syncthreads();
    if (tid < 128) {
        float tot = 0.f;
#pragma unroll
        for (int g = 0; g < 16; g++) tot += red[g][tid];
        atomicAdd(&stats[128 + tid], tot);
    }
}

// ---------------- pooling: 16 partial blocks per group ----------------
__global__ void pool_partial(const float* __restrict__ h, const int* __restrict__ batch,
                             float* __restrict__ part, float* __restrict__ pcnt) {
    int g = blockIdx.x >> 4, c = blockIdx.x & 15;
    int lo = 0, hi = NN;
    while (lo < hi) { int mid = (lo + hi) >> 1; if (batch[mid] < g) lo = mid + 1; else hi = mid; }
    int start = lo;
    lo = start; hi = NN;
    while (lo < hi) { int mid = (lo + hi) >> 1; if (batch[mid] < g + 1) lo = mid + 1; else hi = mid; }
    int end = lo;
    int len = end - start;
    int b0 = start + (int)(((long long)len * c) >> 4);
    int b1 = start + (int)(((long long)len * (c + 1)) >> 4);
    int d = threadIdx.x;
    float s = 0.f;
    for (int r = b0; r < b1; r++) s += h[(size_t)r * 128 + d];
    part[(g * 16 + c) * 128 + d] = s;
    if (c == 0 && d == 0) pcnt[g] = (float)len;
}

// ---------------- classifier: one block per group ----------------
__global__ void classify_kernel(const float* __restrict__ part, const float* __restrict__ pcnt,
                                float* __restrict__ reps,
                                const float* __restrict__ Wc1, const float* __restrict__ bc1,
                                const float* __restrict__ Wc2, const float* __restrict__ bc2,
                                float* __restrict__ logits) {
    __shared__ float rsh[128];
    __shared__ float tsh[128];
    int g = blockIdx.x;
    int d = threadIdx.x;
    float s = 0.f;
#pragma unroll
    for (int c = 0; c < 16; c++) s += part[(g * 16 + c) * 128 + d];
    float inv = 1.0f / fmaxf(pcnt[g], 1.0f);
    float rv = s * inv;
    reps[g * 128 + d] = rv;
    rsh[d] = rv;
    __syncthreads();
    float t = bc1[d];
#pragma unroll
    for (int k = 0; k < 128; k++) t += rsh[k] * Wc1[k * 128 + d];
    tsh[d] = fmaxf(t, 0.f);
    __syncthreads();
    if (d < CC) {
        float s2 = bc2[d];
#pragma unroll
        for (int k = 0; k < 128; k++) s2 += tsh[k] * Wc2[k * CC + d];
        logits[g * CC + d] = s2;
    }
}

// ---------------- launch ----------------
extern "C" void kernel_launch(void* const* d_in, const int* in_sizes, int n_in,
                              void* d_out, int out_size) {
    const float* x     = (const float*)d_in[0];
    const int*   ei    = (const int*)d_in[1];
    const float* ea    = (const float*)d_in[2];
    const int*   batch = (const int*)d_in[3];
    const float* Wg0 = (const float*)d_in[4],  *bg0 = (const float*)d_in[5];
    const float* gamma0 = (const float*)d_in[6], *beta0 = (const float*)d_in[7];
    const float* Wg1 = (const float*)d_in[8],  *bg1 = (const float*)d_in[9];
    const float* gamma1 = (const float*)d_in[10], *beta1 = (const float*)d_in[11];
    const float* Wl1 = (const float*)d_in[12], *bl1 = (const float*)d_in[13];
    const float* Wl2 = (const float*)d_in[14], *bl2 = (const float*)d_in[15];
    const float* Wc1 = (const float*)d_in[16], *bc1 = (const float*)d_in[17];
    const float* Wc2 = (const float*)d_in[18], *bc2 = (const float*)d_in[19];

    float* out = (float*)d_out;
    float* h_out  = out;
    float* reps   = out + (size_t)NN * DD;
    float* logits = out + (size_t)NN * DD + (size_t)GG * DD;

    float *dinv, *stats, *pool, *pcnt;
    __half *bufAh, *bufBh, *wt;
    unsigned long long *packed;
    int *offs, *cur, *bsums;
    int2 *cpack;
    cudaGetSymbolAddress((void**)&bufAh, g_bufA);
    cudaGetSymbolAddress((void**)&bufBh, g_bufB);
    cudaGetSymbolAddress((void**)&dinv, g_dinv);
    cudaGetSymbolAddress((void**)&packed, g_packed);
    cudaGetSymbolAddress((void**)&offs, g_offs);
    cudaGetSymbolAddress((void**)&cur, g_cursor);
    cudaGetSymbolAddress((void**)&bsums, g_bsums);
    cudaGetSymbolAddress((void**)&cpack, g_cpack);
    cudaGetSymbolAddress((void**)&stats, g_stats);
    cudaGetSymbolAddress((void**)&pool, g_pool);
    cudaGetSymbolAddress((void**)&pcnt, g_pcnt);
    cudaGetSymbolAddress((void**)&wt, g_wt);

    float* stats0 = stats;
    float* stats1 = stats + 256;

    cudaFuncSetAttribute(gemm_tc, cudaFuncAttributeMaxDynamicSharedMemorySize, GSMEM);
    cudaFuncSetAttribute(mlp_fused, cudaFuncAttributeMaxDynamicSharedMemorySize, GSMEM);

    const int* src = ei;
    const int* dst = ei + EE;

    const int TB = 256;
    const int gridE4 = (EE / 4 + TB - 1) / TB;      // 1563
    const int gridG  = (NN + 127) / 128;            // 782
    const int gridAg = (NN * 16 + TB - 1) / TB;     // 6250
    const int nScanB = (NN + 1023) / 1024;

    // side stream for CSR build (created per call; not destroyed — capture-safe)
    cudaStream_t sB;
    cudaStreamCreateWithFlags(&sB, cudaStreamNonBlocking);
    cudaEvent_t eFork, eJoin;
    cudaEventCreateWithFlags(&eFork, cudaEventDisableTiming);
    cudaEventCreateWithFlags(&eJoin, cudaEventDisableTiming);

    // prep on main stream, then fork
    prep<<<(NN + TB - 1) / TB, TB>>>(packed, stats, Wg0, Wg1, Wl1, Wl2, wt);
    cudaEventRecord(eFork, 0);
    cudaStreamWaitEvent(sB, eFork, 0);

    // branch B (side stream): CSR build
    hist_kernel<<<gridE4, TB, 0, sB>>>(dst, ea, packed);
    scan1<<<nScanB, 256, 0, sB>>>(packed, offs + 1, bsums, NN, dinv);
    scan2<<<1, 128, 0, sB>>>(bsums, nScanB);
    scan3<<<nScanB, 256, 0, sB>>>(offs + 1, bsums, NN, offs, cur);
    fill_kernel<<<gridE4, TB, 0, sB>>>(src, dst, ea, dinv, cur, cpack);
    cudaEventRecord(eJoin, sB);

    // branch A (main stream): layer-0 GEMM
    gemm_tc<<<gridG, 256, GSMEM>>>(x, nullptr, wt + 0 * 16384, nullptr, nullptr, nullptr, bufAh, NN);

    // join
    cudaStreamWaitEvent(0, eJoin, 0);

    // GCN layer 0
    agg_kernel<<<gridAg, TB>>>(bufAh, dinv, offs, cpack, bg0, bufBh);
    bn_stats<<<BNBLK, 256>>>(bufBh, stats0, NN);

    // GCN layer 1 (bn0 finalize+affine fused into GEMM A-load)
    gemm_tc<<<gridG, 256, GSMEM>>>(nullptr, bufBh, wt + 1 * 16384, stats0, gamma0, beta0, bufAh, NN);
    agg_kernel<<<gridAg, TB>>>(bufAh, dinv, offs, cpack, bg1, bufBh);
    bn_stats<<<BNBLK, 256>>>(bufBh, stats1, NN);

    // fused MLP head (bn1 finalize+affine fused into A-load)
    mlp_fused<<<gridG, 256, GSMEM>>>(bufBh, wt + 2 * 16384, wt + 3 * 16384,
                                     stats1, gamma1, beta1, bl1, bl2, h_out, NN);

    // pooling + classifier
    pool_partial<<<GG * 16, 128>>>(h_out, batch, pool, pcnt);
    classify_kernel<<<GG, 128>>>(pool, pcnt, reps, Wc1, bc1, Wc2, bc2, logits);
}